// round 3
// baseline (speedup 1.0000x reference)
#include <cuda_runtime.h>
#include <cstdint>

#define EMB        128
#define HEADS      4
#define MAX_NODES  50000
#define MAX_EDGES  600000

// ---------------- scratch (static device globals; no allocation) -------------
__device__ float g_qkv[3 * MAX_NODES * EMB];          // Q | K | V   (76.8 MB)
__device__ float g_norm[MAX_NODES * HEADS];           // segment softmax denom
__device__ float g_exp[MAX_EDGES * HEADS];            // per-edge exp(logit)

// ---------------- kernel 0: zero out + norm ---------------------------------
__global__ void zero_kernel(float* __restrict__ out, int n_out, int n_norm) {
    int i = blockIdx.x * blockDim.x + threadIdx.x;
    int stride = gridDim.x * blockDim.x;
    for (int idx = i; idx < n_out; idx += stride) out[idx] = 0.0f;
    for (int idx = i; idx < n_norm; idx += stride) g_norm[idx] = 0.0f;
}

// ---------------- kernel 1: fused QKV projection -----------------------------
// C = A[N,128] @ W[128,128], three weights -> three output slabs of g_qkv.
// BM=128, BN=128 (full width), BK=16, 256 threads, 8x8 micro-tile per thread.
__global__ __launch_bounds__(256) void qkv_gemm(
    const float* __restrict__ A,
    const float* __restrict__ qW,
    const float* __restrict__ kW,
    const float* __restrict__ vW,
    int N)
{
    __shared__ float As[16][136];   // [k][m], padded
    __shared__ float Bs[16][128];   // [k][j]

    const float* W = (blockIdx.x == 0) ? qW : (blockIdx.x == 1) ? kW : vW;
    float* C = g_qkv + (size_t)blockIdx.x * (size_t)N * EMB;

    const int m0  = blockIdx.y * 128;
    const int tid = threadIdx.x;
    const int ty  = tid >> 4;          // 0..15
    const int tx  = tid & 15;          // 0..15

    float acc[8][8];
#pragma unroll
    for (int i = 0; i < 8; i++)
#pragma unroll
        for (int j = 0; j < 8; j++) acc[i][j] = 0.0f;

    for (int kt = 0; kt < EMB; kt += 16) {
        // Load A tile: 128 rows x 16 k  (512 float4, 2 per thread)
#pragma unroll
        for (int it = 0; it < 2; it++) {
            int f  = tid + it * 256;           // 0..511
            int m  = f >> 2;                   // 0..127
            int kk = (f & 3) * 4;              // 0,4,8,12
            float4 v = make_float4(0.f, 0.f, 0.f, 0.f);
            int gm = m0 + m;
            if (gm < N)
                v = *reinterpret_cast<const float4*>(A + (size_t)gm * EMB + kt + kk);
            As[kk + 0][m] = v.x;
            As[kk + 1][m] = v.y;
            As[kk + 2][m] = v.z;
            As[kk + 3][m] = v.w;
        }
        // Load W tile: 16 k x 128 j  (512 float4, 2 per thread)
#pragma unroll
        for (int it = 0; it < 2; it++) {
            int f  = tid + it * 256;
            int kk = f >> 5;                   // 0..15
            int j  = (f & 31) * 4;             // 0..124
            float4 v = *reinterpret_cast<const float4*>(W + (size_t)(kt + kk) * EMB + j);
            *reinterpret_cast<float4*>(&Bs[kk][j]) = v;
        }
        __syncthreads();

#pragma unroll
        for (int kk = 0; kk < 16; kk++) {
            float a[8], b[8];
            float4 a0 = *reinterpret_cast<const float4*>(&As[kk][ty * 8]);
            float4 a1 = *reinterpret_cast<const float4*>(&As[kk][ty * 8 + 4]);
            float4 b0 = *reinterpret_cast<const float4*>(&Bs[kk][tx * 8]);
            float4 b1 = *reinterpret_cast<const float4*>(&Bs[kk][tx * 8 + 4]);
            a[0]=a0.x; a[1]=a0.y; a[2]=a0.z; a[3]=a0.w;
            a[4]=a1.x; a[5]=a1.y; a[6]=a1.z; a[7]=a1.w;
            b[0]=b0.x; b[1]=b0.y; b[2]=b0.z; b[3]=b0.w;
            b[4]=b1.x; b[5]=b1.y; b[6]=b1.z; b[7]=b1.w;
#pragma unroll
            for (int i = 0; i < 8; i++)
#pragma unroll
                for (int j = 0; j < 8; j++)
                    acc[i][j] = fmaf(a[i], b[j], acc[i][j]);
        }
        __syncthreads();
    }

    // Epilogue: float4 stores
#pragma unroll
    for (int i = 0; i < 8; i++) {
        int gm = m0 + ty * 8 + i;
        if (gm < N) {
            float* cp = C + (size_t)gm * EMB + tx * 8;
            *reinterpret_cast<float4*>(cp)     = make_float4(acc[i][0], acc[i][1], acc[i][2], acc[i][3]);
            *reinterpret_cast<float4*>(cp + 4) = make_float4(acc[i][4], acc[i][5], acc[i][6], acc[i][7]);
        }
    }
}

// ---------------- kernel 2: per-edge logits + segment denom ------------------
// One warp per edge. Lane l covers dims [4l, 4l+4); head = lane>>3.
__global__ __launch_bounds__(256) void edge_phase1(
    const int* __restrict__ rows, const int* __restrict__ cols, int E, int N)
{
    int warp = (blockIdx.x * blockDim.x + threadIdx.x) >> 5;
    int lane = threadIdx.x & 31;
    if (warp >= E) return;

    int r = rows[warp];
    int c = cols[warp];

    const float* Q = g_qkv;
    const float* K = g_qkv + (size_t)N * EMB;

    float4 q = *reinterpret_cast<const float4*>(Q + (size_t)r * EMB + lane * 4);
    float4 k = *reinterpret_cast<const float4*>(K + (size_t)c * EMB + lane * 4);

    float p = q.x * k.x;
    p = fmaf(q.y, k.y, p);
    p = fmaf(q.z, k.z, p);
    p = fmaf(q.w, k.w, p);

    // reduce within 8-lane head groups
    p += __shfl_xor_sync(0xffffffffu, p, 1);
    p += __shfl_xor_sync(0xffffffffu, p, 2);
    p += __shfl_xor_sync(0xffffffffu, p, 4);

    if ((lane & 7) == 0) {
        int h = lane >> 3;
        float s  = fminf(fmaxf(p, -10.0f), 10.0f);
        float ex = __expf(s);
        g_exp[(size_t)warp * HEADS + h] = ex;
        atomicAdd(&g_norm[r * HEADS + h], ex);
    }
}

// ---------------- kernel 3: normalize + weighted segment-sum -----------------
// One warp per edge. Lane 0 of each 8-lane head group loads exp/norm and
// broadcasts via shfl (8x fewer scalar loads on the hot kernel).
__global__ __launch_bounds__(256) void edge_phase2(
    const int* __restrict__ rows, const int* __restrict__ cols,
    float* __restrict__ out, int E, int N)
{
    int warp = (blockIdx.x * blockDim.x + threadIdx.x) >> 5;
    int lane = threadIdx.x & 31;
    if (warp >= E) return;

    int r = rows[warp];
    int c = cols[warp];
    int h = lane >> 3;

    float a = 0.0f;
    if ((lane & 7) == 0) {
        float ex = g_exp[(size_t)warp * HEADS + h];
        float nm = g_norm[r * HEADS + h];
        a = ex / (nm + 1e-8f);
    }
    // broadcast from the leader lane of each head group
    a = __shfl_sync(0xffffffffu, a, h << 3);

    const float* V = g_qkv + 2 * (size_t)N * EMB;
    float4 v = *reinterpret_cast<const float4*>(V + (size_t)c * EMB + lane * 4);

    float* op = out + (size_t)r * EMB + lane * 4;
    atomicAdd(op + 0, a * v.x);
    atomicAdd(op + 1, a * v.y);
    atomicAdd(op + 2, a * v.z);
    atomicAdd(op + 3, a * v.w);
}

// ---------------- launch -----------------------------------------------------
extern "C" void kernel_launch(void* const* d_in, const int* in_sizes, int n_in,
                              void* d_out, int out_size)
{
    const float* embeds = (const float*)d_in[0];
    const float* qW     = (const float*)d_in[1];
    const float* kW     = (const float*)d_in[2];
    const float* vW     = (const float*)d_in[3];
    const int*   rows   = (const int*)d_in[4];
    const int*   cols   = (const int*)d_in[5];

    int N = in_sizes[0] / EMB;
    int E = in_sizes[4];
    float* out = (float*)d_out;

    zero_kernel<<<1024, 256>>>(out, N * EMB, N * HEADS);

    dim3 ggrid(3, (N + 127) / 128);
    qkv_gemm<<<ggrid, 256>>>(embeds, qW, kW, vW, N);

    int eblocks = (E + 7) / 8;   // 8 warps (edges) per 256-thread block
    edge_phase1<<<eblocks, 256>>>(rows, cols, E, N);
    edge_phase2<<<eblocks, 256>>>(rows, cols, out, E, N);
}

// round 6
// speedup vs baseline: 1.2373x; 1.2373x over previous
#include <cuda_runtime.h>
#include <cstdint>

#define EMB        128
#define HEADS      4
#define MAX_NODES  50000
#define MAX_EDGES  600000

// ---------------- scratch (static device globals; no allocation) -------------
__device__ float g_qkv[3 * MAX_NODES * EMB];          // Q | K | V   (76.8 MB)
__device__ float g_norm[MAX_NODES * HEADS];           // segment softmax denom
__device__ float g_exp[MAX_EDGES * HEADS];            // per-edge exp(logit)

// ---------------- kernel 0: zero out + norm ---------------------------------
__global__ void zero_kernel(float* __restrict__ out, int n_out, int n_norm) {
    int i = blockIdx.x * blockDim.x + threadIdx.x;
    int stride = gridDim.x * blockDim.x;
    for (int idx = i; idx < n_out; idx += stride) out[idx] = 0.0f;
    for (int idx = i; idx < n_norm; idx += stride) g_norm[idx] = 0.0f;
}

// ---------------- kernel 1: fused QKV projection -----------------------------
// C = A[N,128] @ W[128,128], three weights -> three output slabs of g_qkv.
// BM=128, BN=128 (full width), BK=16, 256 threads, 8x8 micro-tile per thread.
__global__ __launch_bounds__(256) void qkv_gemm(
    const float* __restrict__ A,
    const float* __restrict__ qW,
    const float* __restrict__ kW,
    const float* __restrict__ vW,
    int N)
{
    __shared__ float As[16][136];   // [k][m], padded
    __shared__ float Bs[16][128];   // [k][j]

    const float* W = (blockIdx.x == 0) ? qW : (blockIdx.x == 1) ? kW : vW;
    float* C = g_qkv + (size_t)blockIdx.x * (size_t)N * EMB;

    const int m0  = blockIdx.y * 128;
    const int tid = threadIdx.x;
    const int ty  = tid >> 4;          // 0..15
    const int tx  = tid & 15;          // 0..15

    float acc[8][8];
#pragma unroll
    for (int i = 0; i < 8; i++)
#pragma unroll
        for (int j = 0; j < 8; j++) acc[i][j] = 0.0f;

    for (int kt = 0; kt < EMB; kt += 16) {
        // Load A tile: 128 rows x 16 k  (512 float4, 2 per thread)
#pragma unroll
        for (int it = 0; it < 2; it++) {
            int f  = tid + it * 256;           // 0..511
            int m  = f >> 2;                   // 0..127
            int kk = (f & 3) * 4;              // 0,4,8,12
            float4 v = make_float4(0.f, 0.f, 0.f, 0.f);
            int gm = m0 + m;
            if (gm < N)
                v = *reinterpret_cast<const float4*>(A + (size_t)gm * EMB + kt + kk);
            As[kk + 0][m] = v.x;
            As[kk + 1][m] = v.y;
            As[kk + 2][m] = v.z;
            As[kk + 3][m] = v.w;
        }
        // Load W tile: 16 k x 128 j  (512 float4, 2 per thread)
#pragma unroll
        for (int it = 0; it < 2; it++) {
            int f  = tid + it * 256;
            int kk = f >> 5;                   // 0..15
            int j  = (f & 31) * 4;             // 0..124
            float4 v = *reinterpret_cast<const float4*>(W + (size_t)(kt + kk) * EMB + j);
            *reinterpret_cast<float4*>(&Bs[kk][j]) = v;
        }
        __syncthreads();

#pragma unroll
        for (int kk = 0; kk < 16; kk++) {
            float a[8], b[8];
            float4 a0 = *reinterpret_cast<const float4*>(&As[kk][ty * 8]);
            float4 a1 = *reinterpret_cast<const float4*>(&As[kk][ty * 8 + 4]);
            float4 b0 = *reinterpret_cast<const float4*>(&Bs[kk][tx * 8]);
            float4 b1 = *reinterpret_cast<const float4*>(&Bs[kk][tx * 8 + 4]);
            a[0]=a0.x; a[1]=a0.y; a[2]=a0.z; a[3]=a0.w;
            a[4]=a1.x; a[5]=a1.y; a[6]=a1.z; a[7]=a1.w;
            b[0]=b0.x; b[1]=b0.y; b[2]=b0.z; b[3]=b0.w;
            b[4]=b1.x; b[5]=b1.y; b[6]=b1.z; b[7]=b1.w;
#pragma unroll
            for (int i = 0; i < 8; i++)
#pragma unroll
                for (int j = 0; j < 8; j++)
                    acc[i][j] = fmaf(a[i], b[j], acc[i][j]);
        }
        __syncthreads();
    }

    // Epilogue: float4 stores
#pragma unroll
    for (int i = 0; i < 8; i++) {
        int gm = m0 + ty * 8 + i;
        if (gm < N) {
            float* cp = C + (size_t)gm * EMB + tx * 8;
            *reinterpret_cast<float4*>(cp)     = make_float4(acc[i][0], acc[i][1], acc[i][2], acc[i][3]);
            *reinterpret_cast<float4*>(cp + 4) = make_float4(acc[i][4], acc[i][5], acc[i][6], acc[i][7]);
        }
    }
}

// ---------------- kernel 2: per-edge logits + segment denom ------------------
// One warp per edge. Lane l covers dims [4l, 4l+4); head = lane>>3.
__global__ __launch_bounds__(256) void edge_phase1(
    const int* __restrict__ rows, const int* __restrict__ cols, int E, int N)
{
    int warp = (blockIdx.x * blockDim.x + threadIdx.x) >> 5;
    int lane = threadIdx.x & 31;
    if (warp >= E) return;

    int r = rows[warp];
    int c = cols[warp];

    const float* Q = g_qkv;
    const float* K = g_qkv + (size_t)N * EMB;

    float4 q = *reinterpret_cast<const float4*>(Q + (size_t)r * EMB + lane * 4);
    float4 k = *reinterpret_cast<const float4*>(K + (size_t)c * EMB + lane * 4);

    float p = q.x * k.x;
    p = fmaf(q.y, k.y, p);
    p = fmaf(q.z, k.z, p);
    p = fmaf(q.w, k.w, p);

    // reduce within 8-lane head groups
    p += __shfl_xor_sync(0xffffffffu, p, 1);
    p += __shfl_xor_sync(0xffffffffu, p, 2);
    p += __shfl_xor_sync(0xffffffffu, p, 4);

    if ((lane & 7) == 0) {
        int h = lane >> 3;
        float s  = fminf(fmaxf(p, -10.0f), 10.0f);
        float ex = __expf(s);
        g_exp[(size_t)warp * HEADS + h] = ex;
        atomicAdd(&g_norm[r * HEADS + h], ex);
    }
}

// ---------------- kernel 3: normalize + weighted segment-sum -----------------
// One warp per edge. Vectorized reduction: one red.global.add.v4.f32 per lane
// replaces four scalar atomicAdds (76.8M -> 19.2M RED ops).
__global__ __launch_bounds__(256) void edge_phase2(
    const int* __restrict__ rows, const int* __restrict__ cols,
    float* __restrict__ out, int E, int N)
{
    int warp = (blockIdx.x * blockDim.x + threadIdx.x) >> 5;
    int lane = threadIdx.x & 31;
    if (warp >= E) return;

    int r = rows[warp];
    int c = cols[warp];
    int h = lane >> 3;

    float a = 0.0f;
    if ((lane & 7) == 0) {
        float ex = g_exp[(size_t)warp * HEADS + h];
        float nm = g_norm[r * HEADS + h];
        a = ex / (nm + 1e-8f);
    }
    // broadcast from the leader lane of each head group
    a = __shfl_sync(0xffffffffu, a, h << 3);

    const float* V = g_qkv + 2 * (size_t)N * EMB;
    float4 v = *reinterpret_cast<const float4*>(V + (size_t)c * EMB + lane * 4);

    float* op = out + (size_t)r * EMB + lane * 4;   // 16B-aligned
    asm volatile("red.global.add.v4.f32 [%0], {%1, %2, %3, %4};"
                 :: "l"(op), "f"(a * v.x), "f"(a * v.y),
                    "f"(a * v.z), "f"(a * v.w)
                 : "memory");
}

// ---------------- launch -----------------------------------------------------
extern "C" void kernel_launch(void* const* d_in, const int* in_sizes, int n_in,
                              void* d_out, int out_size)
{
    const float* embeds = (const float*)d_in[0];
    const float* qW     = (const float*)d_in[1];
    const float* kW     = (const float*)d_in[2];
    const float* vW     = (const float*)d_in[3];
    const int*   rows   = (const int*)d_in[4];
    const int*   cols   = (const int*)d_in[5];

    int N = in_sizes[0] / EMB;
    int E = in_sizes[4];
    float* out = (float*)d_out;

    zero_kernel<<<1024, 256>>>(out, N * EMB, N * HEADS);

    dim3 ggrid(3, (N + 127) / 128);
    qkv_gemm<<<ggrid, 256>>>(embeds, qW, kW, vW, N);

    int eblocks = (E + 7) / 8;   // 8 warps (edges) per 256-thread block
    edge_phase1<<<eblocks, 256>>>(rows, cols, E, N);
    edge_phase2<<<eblocks, 256>>>(rows, cols, out, E, N);
}

// round 9
// speedup vs baseline: 1.5691x; 1.2682x over previous
#include <cuda_runtime.h>
#include <cstdint>

#define EMB        128
#define HEADS      4
#define DH         32                 // EMB / HEADS
#define MAX_NODES  50000
#define MAX_EDGES  600000

// ---------------- scratch (static device globals; no allocation) -------------
__device__ float g_qkv[3 * MAX_NODES * EMB];          // Q | K | V   (76.8 MB)
__device__ float g_norm[MAX_NODES * HEADS];           // segment softmax denom

// ---------------- kernel 0: zero out + norm ---------------------------------
__global__ void zero_kernel(float* __restrict__ out, int n_out, int n_norm) {
    int i = blockIdx.x * blockDim.x + threadIdx.x;
    int stride = gridDim.x * blockDim.x;
    for (int idx = i; idx < n_out; idx += stride) out[idx] = 0.0f;
    for (int idx = i; idx < n_norm; idx += stride) g_norm[idx] = 0.0f;
}

// ---------------- kernel 1: fused QKV projection -----------------------------
// C = A[N,128] @ W[128,128], three weights -> three output slabs of g_qkv.
// BM=128, BN=128 (full width), BK=16, 256 threads, 8x8 micro-tile per thread.
__global__ __launch_bounds__(256) void qkv_gemm(
    const float* __restrict__ A,
    const float* __restrict__ qW,
    const float* __restrict__ kW,
    const float* __restrict__ vW,
    int N)
{
    __shared__ float As[16][136];   // [k][m], padded
    __shared__ float Bs[16][128];   // [k][j]

    const float* W = (blockIdx.x == 0) ? qW : (blockIdx.x == 1) ? kW : vW;
    float* C = g_qkv + (size_t)blockIdx.x * (size_t)N * EMB;

    const int m0  = blockIdx.y * 128;
    const int tid = threadIdx.x;
    const int ty  = tid >> 4;          // 0..15
    const int tx  = tid & 15;          // 0..15

    float acc[8][8];
#pragma unroll
    for (int i = 0; i < 8; i++)
#pragma unroll
        for (int j = 0; j < 8; j++) acc[i][j] = 0.0f;

    for (int kt = 0; kt < EMB; kt += 16) {
#pragma unroll
        for (int it = 0; it < 2; it++) {
            int f  = tid + it * 256;           // 0..511
            int m  = f >> 2;                   // 0..127
            int kk = (f & 3) * 4;              // 0,4,8,12
            float4 v = make_float4(0.f, 0.f, 0.f, 0.f);
            int gm = m0 + m;
            if (gm < N)
                v = *reinterpret_cast<const float4*>(A + (size_t)gm * EMB + kt + kk);
            As[kk + 0][m] = v.x;
            As[kk + 1][m] = v.y;
            As[kk + 2][m] = v.z;
            As[kk + 3][m] = v.w;
        }
#pragma unroll
        for (int it = 0; it < 2; it++) {
            int f  = tid + it * 256;
            int kk = f >> 5;                   // 0..15
            int j  = (f & 31) * 4;             // 0..124
            float4 v = *reinterpret_cast<const float4*>(W + (size_t)(kt + kk) * EMB + j);
            *reinterpret_cast<float4*>(&Bs[kk][j]) = v;
        }
        __syncthreads();

#pragma unroll
        for (int kk = 0; kk < 16; kk++) {
            float a[8], b[8];
            float4 a0 = *reinterpret_cast<const float4*>(&As[kk][ty * 8]);
            float4 a1 = *reinterpret_cast<const float4*>(&As[kk][ty * 8 + 4]);
            float4 b0 = *reinterpret_cast<const float4*>(&Bs[kk][tx * 8]);
            float4 b1 = *reinterpret_cast<const float4*>(&Bs[kk][tx * 8 + 4]);
            a[0]=a0.x; a[1]=a0.y; a[2]=a0.z; a[3]=a0.w;
            a[4]=a1.x; a[5]=a1.y; a[6]=a1.z; a[7]=a1.w;
            b[0]=b0.x; b[1]=b0.y; b[2]=b0.z; b[3]=b0.w;
            b[4]=b1.x; b[5]=b1.y; b[6]=b1.z; b[7]=b1.w;
#pragma unroll
            for (int i = 0; i < 8; i++)
#pragma unroll
                for (int j = 0; j < 8; j++)
                    acc[i][j] = fmaf(a[i], b[j], acc[i][j]);
        }
        __syncthreads();
    }

#pragma unroll
    for (int i = 0; i < 8; i++) {
        int gm = m0 + ty * 8 + i;
        if (gm < N) {
            float* cp = C + (size_t)gm * EMB + tx * 8;
            *reinterpret_cast<float4*>(cp)     = make_float4(acc[i][0], acc[i][1], acc[i][2], acc[i][3]);
            *reinterpret_cast<float4*>(cp + 4) = make_float4(acc[i][4], acc[i][5], acc[i][6], acc[i][7]);
        }
    }
}

// ---------------- kernel 2: fused edge pass ----------------------------------
// One warp per edge. Gathers q,k,v (3 independent 16B loads/lane, issued
// before any consumer), computes per-head logits via xor-shuffle reduce
// (every lane ends with its head's sum), accumulates:
//   g_norm[r,h] += exp(clip(logit))        (1 scalar atomic per head group)
//   out[r,:]    += exp * V[c,:]            (1 RED.128 per lane, UNNORMALIZED)
// Normalization is deferred to scale_kernel (per-row constant divisor).
__global__ __launch_bounds__(256) void edge_fused(
    const int* __restrict__ rows, const int* __restrict__ cols,
    float* __restrict__ out, int E, int N)
{
    int warp = (blockIdx.x * blockDim.x + threadIdx.x) >> 5;
    int lane = threadIdx.x & 31;
    if (warp >= E) return;

    int r = rows[warp];
    int c = cols[warp];

    const float* Q = g_qkv;
    const float* K = g_qkv + (size_t)N * EMB;
    const float* V = g_qkv + 2 * (size_t)N * EMB;

    // issue all three gathers up front (independent -> MLP=3)
    float4 q = *reinterpret_cast<const float4*>(Q + (size_t)r * EMB + lane * 4);
    float4 k = *reinterpret_cast<const float4*>(K + (size_t)c * EMB + lane * 4);
    float4 v = *reinterpret_cast<const float4*>(V + (size_t)c * EMB + lane * 4);

    float p = q.x * k.x;
    p = fmaf(q.y, k.y, p);
    p = fmaf(q.z, k.z, p);
    p = fmaf(q.w, k.w, p);

    // reduce within 8-lane head groups; all 8 lanes end with the head sum
    p += __shfl_xor_sync(0xffffffffu, p, 1);
    p += __shfl_xor_sync(0xffffffffu, p, 2);
    p += __shfl_xor_sync(0xffffffffu, p, 4);

    float s = fminf(fmaxf(p, -10.0f), 10.0f);
    float a = __expf(s);

    if ((lane & 7) == 0)
        atomicAdd(&g_norm[r * HEADS + (lane >> 3)], a);

    float* op = out + (size_t)r * EMB + lane * 4;   // 16B-aligned
    asm volatile("red.global.add.v4.f32 [%0], {%1, %2, %3, %4};"
                 :: "l"(op), "f"(a * v.x), "f"(a * v.y),
                    "f"(a * v.z), "f"(a * v.w)
                 : "memory");
}

// ---------------- kernel 3: deferred normalization ---------------------------
// out[n, d] /= (norm[n, d>>5] + 1e-8).  float4 per thread (head-aligned).
__global__ __launch_bounds__(256) void scale_kernel(
    float* __restrict__ out, int N)
{
    int i = blockIdx.x * blockDim.x + threadIdx.x;
    int total = N * (EMB / 4);
    int stride = gridDim.x * blockDim.x;
    for (int idx = i; idx < total; idx += stride) {
        int n  = idx >> 5;            // EMB/4 = 32 float4 per row
        int d4 = idx & 31;            // float4 index in row
        int h  = d4 >> 3;             // 8 float4 per head
        float inv = 1.0f / (g_norm[n * HEADS + h] + 1e-8f);
        float4* p = reinterpret_cast<float4*>(out) + idx;
        float4 vv = *p;
        vv.x *= inv; vv.y *= inv; vv.z *= inv; vv.w *= inv;
        *p = vv;
    }
}

// ---------------- launch -----------------------------------------------------
extern "C" void kernel_launch(void* const* d_in, const int* in_sizes, int n_in,
                              void* d_out, int out_size)
{
    const float* embeds = (const float*)d_in[0];
    const float* qW     = (const float*)d_in[1];
    const float* kW     = (const float*)d_in[2];
    const float* vW     = (const float*)d_in[3];
    const int*   rows   = (const int*)d_in[4];
    const int*   cols   = (const int*)d_in[5];

    int N = in_sizes[0] / EMB;
    int E = in_sizes[4];
    float* out = (float*)d_out;

    zero_kernel<<<1024, 256>>>(out, N * EMB, N * HEADS);

    dim3 ggrid(3, (N + 127) / 128);
    qkv_gemm<<<ggrid, 256>>>(embeds, qW, kW, vW, N);

    int eblocks = (E + 7) / 8;   // 8 warps (edges) per 256-thread block
    edge_fused<<<eblocks, 256>>>(rows, cols, out, E, N);

    scale_kernel<<<592, 256>>>(out, N);
}

// round 12
// speedup vs baseline: 1.8091x; 1.1530x over previous
#include <cuda_runtime.h>
#include <cuda_bf16.h>
#include <cstdint>

#define EMB        128
#define HEADS      4
#define MAX_NODES  50000
#define MAX_EDGES  600000

// ---------------- scratch (static device globals; no allocation) -------------
__device__ float g_qkv[3 * MAX_NODES * EMB];            // Q | K | V  (76.8 MB)
__device__ float g_norm[MAX_NODES * HEADS];             // segment softmax denom
__device__ __nv_bfloat16 g_wt_hi[3 * EMB * EMB];        // W^T split, hi part
__device__ __nv_bfloat16 g_wt_lo[3 * EMB * EMB];        // W^T split, lo part

// ---------------- smem geometry ----------------------------------------------
// Row-major bf16 tiles, 128 rows x 128 cols, row stride padded to 272 bytes
// (68 words == 4 banks rotation per row -> conflict-free ldmatrix).
#define ROW_B    272
#define TILE_B   (128 * ROW_B)          // 34816
#define SM_A_HI  0
#define SM_A_LO  TILE_B
#define SM_B_HI  (2 * TILE_B)
#define SM_B_LO  (3 * TILE_B)
#define SM_TOTAL (4 * TILE_B)           // 139264 B dynamic smem

__device__ __forceinline__ uint32_t smem_u32(const void* p) {
    uint32_t a;
    asm("{ .reg .u64 t; cvta.to.shared.u64 t, %1; cvt.u32.u64 %0, t; }"
        : "=r"(a) : "l"(p));
    return a;
}

// ---------------- kernel 0: zero out + norm ---------------------------------
__global__ void zero_kernel(float* __restrict__ out, int n_out, int n_norm) {
    int i = blockIdx.x * blockDim.x + threadIdx.x;
    int stride = gridDim.x * blockDim.x;
    for (int idx = i; idx < n_out; idx += stride) out[idx] = 0.0f;
    for (int idx = i; idx < n_norm; idx += stride) g_norm[idx] = 0.0f;
}

// ---------------- kernel 0b: split weights to bf16 hi/lo, transposed ---------
// g_wt_*[w][j][k] = split(W_w[k][j])   (B stored [n][k], k contiguous)
__global__ void prep_weights(const float* __restrict__ qW,
                             const float* __restrict__ kW,
                             const float* __restrict__ vW) {
    int t = blockIdx.x * blockDim.x + threadIdx.x;
    if (t >= 3 * EMB * EMB) return;
    int w   = t / (EMB * EMB);
    int rem = t - w * (EMB * EMB);
    int j   = rem >> 7;
    int k   = rem & 127;
    const float* W = (w == 0) ? qW : (w == 1) ? kW : vW;
    float x = W[k * EMB + j];
    __nv_bfloat16 hi = __float2bfloat16(x);
    __nv_bfloat16 lo = __float2bfloat16(x - __bfloat162float(hi));
    g_wt_hi[t] = hi;
    g_wt_lo[t] = lo;
}

// ---------------- kernel 1: QKV projection via mma.sync bf16x3 ---------------
// D = Ah@Bh + Ah@Bl + Al@Bh, fp32 accumulate.  grid (3, mtiles), 8 warps.
// Warp (wm,wn) tile = 32 x 64 -> 16 m16n8 fragments.
__global__ __launch_bounds__(256, 1) void qkv_gemm_mma(
    const float* __restrict__ A, int N)
{
    extern __shared__ char smem[];
    uint32_t sb = smem_u32(smem);

    int tid  = threadIdx.x;
    int warp = tid >> 5;
    int lane = tid & 31;
    int w    = blockIdx.x;
    int m0   = blockIdx.y * 128;

    // ---- stage A: fp32 -> bf16 hi/lo into padded smem -----------------------
    {
        int m  = tid >> 1;              // 0..127
        int h  = tid & 1;               // half row
        int gm = m0 + m;
        const float* ap = A + (size_t)gm * EMB;
#pragma unroll
        for (int g = 0; g < 8; g++) {
            int col = h * 64 + g * 8;
            float4 f0 = make_float4(0.f, 0.f, 0.f, 0.f);
            float4 f1 = make_float4(0.f, 0.f, 0.f, 0.f);
            if (gm < N) {
                f0 = *reinterpret_cast<const float4*>(ap + col);
                f1 = *reinterpret_cast<const float4*>(ap + col + 4);
            }
            float x[8] = {f0.x, f0.y, f0.z, f0.w, f1.x, f1.y, f1.z, f1.w};
            uint32_t hi[4], lo[4];
#pragma unroll
            for (int p = 0; p < 4; p++) {
                __nv_bfloat16 h0 = __float2bfloat16(x[2*p]);
                __nv_bfloat16 h1 = __float2bfloat16(x[2*p+1]);
                __nv_bfloat16 l0 = __float2bfloat16(x[2*p]   - __bfloat162float(h0));
                __nv_bfloat16 l1 = __float2bfloat16(x[2*p+1] - __bfloat162float(h1));
                hi[p] = (uint32_t)__bfloat16_as_ushort(h0) |
                        ((uint32_t)__bfloat16_as_ushort(h1) << 16);
                lo[p] = (uint32_t)__bfloat16_as_ushort(l0) |
                        ((uint32_t)__bfloat16_as_ushort(l1) << 16);
            }
            uint32_t off = (uint32_t)m * ROW_B + (uint32_t)col * 2;
            *reinterpret_cast<uint4*>(smem + SM_A_HI + off) = make_uint4(hi[0], hi[1], hi[2], hi[3]);
            *reinterpret_cast<uint4*>(smem + SM_A_LO + off) = make_uint4(lo[0], lo[1], lo[2], lo[3]);
        }
    }
    // ---- stage B: pre-split W^T (bf16) into padded smem ---------------------
    {
        int n = tid >> 1;
        int h = tid & 1;
        const __nv_bfloat16* bh = g_wt_hi + (size_t)w * EMB * EMB + (size_t)n * EMB;
        const __nv_bfloat16* bl = g_wt_lo + (size_t)w * EMB * EMB + (size_t)n * EMB;
#pragma unroll
        for (int g = 0; g < 4; g++) {
            int col = h * 64 + g * 16;
            uint32_t off = (uint32_t)n * ROW_B + (uint32_t)col * 2;
            *reinterpret_cast<uint4*>(smem + SM_B_HI + off) =
                *reinterpret_cast<const uint4*>(bh + col);
            *reinterpret_cast<uint4*>(smem + SM_B_HI + off + 16) =
                *reinterpret_cast<const uint4*>(bh + col + 8);
            *reinterpret_cast<uint4*>(smem + SM_B_LO + off) =
                *reinterpret_cast<const uint4*>(bl + col);
            *reinterpret_cast<uint4*>(smem + SM_B_LO + off + 16) =
                *reinterpret_cast<const uint4*>(bl + col + 8);
        }
    }
    __syncthreads();

    const int wm = (warp & 3) * 32;      // warp m offset
    const int wn = (warp >> 2) * 64;     // warp n offset

    float acc[16][4];
#pragma unroll
    for (int t = 0; t < 16; t++)
#pragma unroll
        for (int q = 0; q < 4; q++) acc[t][q] = 0.0f;

    const int g8 = lane >> 3;            // ldmatrix matrix id 0..3
    const int r8 = lane & 7;             // row within matrix

#pragma unroll
    for (int pass = 0; pass < 3; pass++) {
        uint32_t ua = sb + ((pass == 2) ? SM_A_LO : SM_A_HI);
        uint32_t ub = sb + ((pass == 1) ? SM_B_LO : SM_B_HI);

#pragma unroll
        for (int ks = 0; ks < 8; ks++) {
            int k0 = ks * 16;

            // A fragments: 2 x ldmatrix.x4 (m16k16 each)
            uint32_t a[2][4];
#pragma unroll
            for (int i = 0; i < 2; i++) {
                uint32_t addr = ua
                    + (uint32_t)(wm + i*16 + (g8 & 1)*8 + r8) * ROW_B
                    + (uint32_t)(k0 + (g8 >> 1)*8) * 2;
                asm volatile(
                    "ldmatrix.sync.aligned.m8n8.x4.shared.b16 {%0,%1,%2,%3}, [%4];"
                    : "=r"(a[i][0]), "=r"(a[i][1]), "=r"(a[i][2]), "=r"(a[i][3])
                    : "r"(addr));
            }
            // B fragments: 4 x ldmatrix.x4, each yields two n8k16 frags
            uint32_t b[8][2];
#pragma unroll
            for (int j2 = 0; j2 < 4; j2++) {
                uint32_t addr = ub
                    + (uint32_t)(wn + j2*16 + (g8 >> 1)*8 + r8) * ROW_B
                    + (uint32_t)(k0 + (g8 & 1)*8) * 2;
                uint32_t x0, x1, x2, x3;
                asm volatile(
                    "ldmatrix.sync.aligned.m8n8.x4.shared.b16 {%0,%1,%2,%3}, [%4];"
                    : "=r"(x0), "=r"(x1), "=r"(x2), "=r"(x3)
                    : "r"(addr));
                b[j2*2    ][0] = x0; b[j2*2    ][1] = x1;
                b[j2*2 + 1][0] = x2; b[j2*2 + 1][1] = x3;
            }
            // 16 MMAs
#pragma unroll
            for (int i = 0; i < 2; i++)
#pragma unroll
                for (int j = 0; j < 8; j++) {
                    int t = i * 8 + j;
                    asm volatile(
                        "mma.sync.aligned.m16n8k16.row.col.f32.bf16.bf16.f32 "
                        "{%0,%1,%2,%3}, {%4,%5,%6,%7}, {%8,%9}, {%0,%1,%2,%3};"
                        : "+f"(acc[t][0]), "+f"(acc[t][1]),
                          "+f"(acc[t][2]), "+f"(acc[t][3])
                        : "r"(a[i][0]), "r"(a[i][1]), "r"(a[i][2]), "r"(a[i][3]),
                          "r"(b[j][0]), "r"(b[j][1]));
                }
        }
    }

    // ---- epilogue: fragment -> global ---------------------------------------
    {
        float* C = g_qkv + (size_t)w * (size_t)N * EMB;
        int qrow = lane >> 2;            // 0..7
        int qcol = (lane & 3) * 2;       // 0,2,4,6
#pragma unroll
        for (int t = 0; t < 16; t++) {
            int i = t >> 3, j = t & 7;
            int gr = m0 + wm + i*16 + qrow;
            int gc = wn + j*8 + qcol;
            if (gr < N)
                *reinterpret_cast<float2*>(C + (size_t)gr * EMB + gc) =
                    make_float2(acc[t][0], acc[t][1]);
            int gr2 = gr + 8;
            if (gr2 < N)
                *reinterpret_cast<float2*>(C + (size_t)gr2 * EMB + gc) =
                    make_float2(acc[t][2], acc[t][3]);
        }
    }
}

// ---------------- kernel 2: fused edge pass ----------------------------------
__global__ __launch_bounds__(256) void edge_fused(
    const int* __restrict__ rows, const int* __restrict__ cols,
    float* __restrict__ out, int E, int N)
{
    int warp = (blockIdx.x * blockDim.x + threadIdx.x) >> 5;
    int lane = threadIdx.x & 31;
    if (warp >= E) return;

    int r = rows[warp];
    int c = cols[warp];

    const float* Q = g_qkv;
    const float* K = g_qkv + (size_t)N * EMB;
    const float* V = g_qkv + 2 * (size_t)N * EMB;

    float4 q = *reinterpret_cast<const float4*>(Q + (size_t)r * EMB + lane * 4);
    float4 k = *reinterpret_cast<const float4*>(K + (size_t)c * EMB + lane * 4);
    float4 v = *reinterpret_cast<const float4*>(V + (size_t)c * EMB + lane * 4);

    float p = q.x * k.x;
    p = fmaf(q.y, k.y, p);
    p = fmaf(q.z, k.z, p);
    p = fmaf(q.w, k.w, p);

    p += __shfl_xor_sync(0xffffffffu, p, 1);
    p += __shfl_xor_sync(0xffffffffu, p, 2);
    p += __shfl_xor_sync(0xffffffffu, p, 4);

    float s = fminf(fmaxf(p, -10.0f), 10.0f);
    float a = __expf(s);

    if ((lane & 7) == 0)
        atomicAdd(&g_norm[r * HEADS + (lane >> 3)], a);

    float* op = out + (size_t)r * EMB + lane * 4;
    asm volatile("red.global.add.v4.f32 [%0], {%1, %2, %3, %4};"
                 :: "l"(op), "f"(a * v.x), "f"(a * v.y),
                    "f"(a * v.z), "f"(a * v.w)
                 : "memory");
}

// ---------------- kernel 3: deferred normalization ---------------------------
__global__ __launch_bounds__(256) void scale_kernel(float* __restrict__ out, int N)
{
    int idx = blockIdx.x * blockDim.x + threadIdx.x;
    int total = N * (EMB / 4);
    if (idx >= total) return;
    int n  = idx >> 5;
    int d4 = idx & 31;
    int h  = d4 >> 3;
    float inv = 1.0f / (g_norm[n * HEADS + h] + 1e-8f);
    float4* p = reinterpret_cast<float4*>(out) + idx;
    float4 vv = *p;
    vv.x *= inv; vv.y *= inv; vv.z *= inv; vv.w *= inv;
    *p = vv;
}

// ---------------- launch -----------------------------------------------------
extern "C" void kernel_launch(void* const* d_in, const int* in_sizes, int n_in,
                              void* d_out, int out_size)
{
    const float* embeds = (const float*)d_in[0];
    const float* qW     = (const float*)d_in[1];
    const float* kW     = (const float*)d_in[2];
    const float* vW     = (const float*)d_in[3];
    const int*   rows   = (const int*)d_in[4];
    const int*   cols   = (const int*)d_in[5];

    int N = in_sizes[0] / EMB;
    int E = in_sizes[4];
    float* out = (float*)d_out;

    static bool attr_set = false;
    if (!attr_set) {
        cudaFuncSetAttribute(qkv_gemm_mma,
                             cudaFuncAttributeMaxDynamicSharedMemorySize, SM_TOTAL);
        attr_set = true;
    }

    zero_kernel<<<2048, 256>>>(out, N * EMB, N * HEADS);
    prep_weights<<<(3 * EMB * EMB + 255) / 256, 256>>>(qW, kW, vW);

    int mtiles = (N + 127) / 128;
    qkv_gemm_mma<<<dim3(3, mtiles), 256, SM_TOTAL>>>(embeds, N);

    int eblocks = (E + 7) / 8;
    edge_fused<<<eblocks, 256>>>(rows, cols, out, E, N);

    scale_kernel<<<(N * (EMB / 4) + 255) / 256, 256>>>(out, N);
}

// round 13
// speedup vs baseline: 2.0126x; 1.1125x over previous
#include <cuda_runtime.h>
#include <cuda_bf16.h>
#include <cstdint>

#define EMB        128
#define HEADS      4
#define MAX_NODES  50000
#define MAX_EDGES  600000

// ---------------- scratch (static device globals; no allocation) -------------
__device__ float g_qkv[3 * MAX_NODES * EMB];            // Q | K | V  (76.8 MB)
__device__ float g_norm[MAX_NODES * HEADS];             // segment softmax denom
__device__ __nv_bfloat16 g_wt_hi[3 * EMB * EMB];        // W^T split, hi part
__device__ __nv_bfloat16 g_wt_lo[3 * EMB * EMB];        // W^T split, lo part

// ---------------- smem geometry ----------------------------------------------
#define ROW_B    272
#define TILE_B   (128 * ROW_B)          // 34816
#define SM_A_HI  0
#define SM_A_LO  TILE_B
#define SM_B_HI  (2 * TILE_B)
#define SM_B_LO  (3 * TILE_B)
#define SM_TOTAL (4 * TILE_B)           // 139264 B dynamic smem

__device__ __forceinline__ uint32_t smem_u32(const void* p) {
    uint32_t a;
    asm("{ .reg .u64 t; cvta.to.shared.u64 t, %1; cvt.u32.u64 %0, t; }"
        : "=r"(a) : "l"(p));
    return a;
}

// ---------------- kernel 0: zero out + norm ---------------------------------
__global__ void zero_kernel(float* __restrict__ out, int n_out, int n_norm) {
    int i = blockIdx.x * blockDim.x + threadIdx.x;
    int stride = gridDim.x * blockDim.x;
    for (int idx = i; idx < n_out; idx += stride) out[idx] = 0.0f;
    for (int idx = i; idx < n_norm; idx += stride) g_norm[idx] = 0.0f;
}

// ---------------- kernel 0b: split weights to bf16 hi/lo, transposed ---------
__global__ void prep_weights(const float* __restrict__ qW,
                             const float* __restrict__ kW,
                             const float* __restrict__ vW) {
    int t = blockIdx.x * blockDim.x + threadIdx.x;
    if (t >= 3 * EMB * EMB) return;
    int w   = t / (EMB * EMB);
    int rem = t - w * (EMB * EMB);
    int j   = rem >> 7;
    int k   = rem & 127;
    const float* W = (w == 0) ? qW : (w == 1) ? kW : vW;
    float x = W[k * EMB + j];
    __nv_bfloat16 hi = __float2bfloat16(x);
    __nv_bfloat16 lo = __float2bfloat16(x - __bfloat162float(hi));
    g_wt_hi[t] = hi;
    g_wt_lo[t] = lo;
}

// ---------------- kernel 1: QKV projection via mma.sync bf16x3 ---------------
__global__ __launch_bounds__(256, 1) void qkv_gemm_mma(
    const float* __restrict__ A, int N)
{
    extern __shared__ char smem[];
    uint32_t sb = smem_u32(smem);

    int tid  = threadIdx.x;
    int warp = tid >> 5;
    int lane = tid & 31;
    int w    = blockIdx.x;
    int m0   = blockIdx.y * 128;

    // ---- stage A: fp32 -> bf16 hi/lo into padded smem -----------------------
    {
        int m  = tid >> 1;
        int h  = tid & 1;
        int gm = m0 + m;
        const float* ap = A + (size_t)gm * EMB;
#pragma unroll
        for (int g = 0; g < 8; g++) {
            int col = h * 64 + g * 8;
            float4 f0 = make_float4(0.f, 0.f, 0.f, 0.f);
            float4 f1 = make_float4(0.f, 0.f, 0.f, 0.f);
            if (gm < N) {
                f0 = *reinterpret_cast<const float4*>(ap + col);
                f1 = *reinterpret_cast<const float4*>(ap + col + 4);
            }
            float x[8] = {f0.x, f0.y, f0.z, f0.w, f1.x, f1.y, f1.z, f1.w};
            uint32_t hi[4], lo[4];
#pragma unroll
            for (int p = 0; p < 4; p++) {
                __nv_bfloat16 h0 = __float2bfloat16(x[2*p]);
                __nv_bfloat16 h1 = __float2bfloat16(x[2*p+1]);
                __nv_bfloat16 l0 = __float2bfloat16(x[2*p]   - __bfloat162float(h0));
                __nv_bfloat16 l1 = __float2bfloat16(x[2*p+1] - __bfloat162float(h1));
                hi[p] = (uint32_t)__bfloat16_as_ushort(h0) |
                        ((uint32_t)__bfloat16_as_ushort(h1) << 16);
                lo[p] = (uint32_t)__bfloat16_as_ushort(l0) |
                        ((uint32_t)__bfloat16_as_ushort(l1) << 16);
            }
            uint32_t off = (uint32_t)m * ROW_B + (uint32_t)col * 2;
            *reinterpret_cast<uint4*>(smem + SM_A_HI + off) = make_uint4(hi[0], hi[1], hi[2], hi[3]);
            *reinterpret_cast<uint4*>(smem + SM_A_LO + off) = make_uint4(lo[0], lo[1], lo[2], lo[3]);
        }
    }
    // ---- stage B: pre-split W^T (bf16) into padded smem ---------------------
    {
        int n = tid >> 1;
        int h = tid & 1;
        const __nv_bfloat16* bh = g_wt_hi + (size_t)w * EMB * EMB + (size_t)n * EMB;
        const __nv_bfloat16* bl = g_wt_lo + (size_t)w * EMB * EMB + (size_t)n * EMB;
#pragma unroll
        for (int g = 0; g < 4; g++) {
            int col = h * 64 + g * 16;
            uint32_t off = (uint32_t)n * ROW_B + (uint32_t)col * 2;
            *reinterpret_cast<uint4*>(smem + SM_B_HI + off) =
                *reinterpret_cast<const uint4*>(bh + col);
            *reinterpret_cast<uint4*>(smem + SM_B_HI + off + 16) =
                *reinterpret_cast<const uint4*>(bh + col + 8);
            *reinterpret_cast<uint4*>(smem + SM_B_LO + off) =
                *reinterpret_cast<const uint4*>(bl + col);
            *reinterpret_cast<uint4*>(smem + SM_B_LO + off + 16) =
                *reinterpret_cast<const uint4*>(bl + col + 8);
        }
    }
    __syncthreads();

    const int wm = (warp & 3) * 32;
    const int wn = (warp >> 2) * 64;

    float acc[16][4];
#pragma unroll
    for (int t = 0; t < 16; t++)
#pragma unroll
        for (int q = 0; q < 4; q++) acc[t][q] = 0.0f;

    const int g8 = lane >> 3;
    const int r8 = lane & 7;

#pragma unroll
    for (int pass = 0; pass < 3; pass++) {
        uint32_t ua = sb + ((pass == 2) ? SM_A_LO : SM_A_HI);
        uint32_t ub = sb + ((pass == 1) ? SM_B_LO : SM_B_HI);

#pragma unroll
        for (int ks = 0; ks < 8; ks++) {
            int k0 = ks * 16;

            uint32_t a[2][4];
#pragma unroll
            for (int i = 0; i < 2; i++) {
                uint32_t addr = ua
                    + (uint32_t)(wm + i*16 + (g8 & 1)*8 + r8) * ROW_B
                    + (uint32_t)(k0 + (g8 >> 1)*8) * 2;
                asm volatile(
                    "ldmatrix.sync.aligned.m8n8.x4.shared.b16 {%0,%1,%2,%3}, [%4];"
                    : "=r"(a[i][0]), "=r"(a[i][1]), "=r"(a[i][2]), "=r"(a[i][3])
                    : "r"(addr));
            }
            uint32_t b[8][2];
#pragma unroll
            for (int j2 = 0; j2 < 4; j2++) {
                uint32_t addr = ub
                    + (uint32_t)(wn + j2*16 + (g8 >> 1)*8 + r8) * ROW_B
                    + (uint32_t)(k0 + (g8 & 1)*8) * 2;
                uint32_t x0, x1, x2, x3;
                asm volatile(
                    "ldmatrix.sync.aligned.m8n8.x4.shared.b16 {%0,%1,%2,%3}, [%4];"
                    : "=r"(x0), "=r"(x1), "=r"(x2), "=r"(x3)
                    : "r"(addr));
                b[j2*2    ][0] = x0; b[j2*2    ][1] = x1;
                b[j2*2 + 1][0] = x2; b[j2*2 + 1][1] = x3;
            }
#pragma unroll
            for (int i = 0; i < 2; i++)
#pragma unroll
                for (int j = 0; j < 8; j++) {
                    int t = i * 8 + j;
                    asm volatile(
                        "mma.sync.aligned.m16n8k16.row.col.f32.bf16.bf16.f32 "
                        "{%0,%1,%2,%3}, {%4,%5,%6,%7}, {%8,%9}, {%0,%1,%2,%3};"
                        : "+f"(acc[t][0]), "+f"(acc[t][1]),
                          "+f"(acc[t][2]), "+f"(acc[t][3])
                        : "r"(a[i][0]), "r"(a[i][1]), "r"(a[i][2]), "r"(a[i][3]),
                          "r"(b[j][0]), "r"(b[j][1]));
                }
        }
    }

    {
        float* C = g_qkv + (size_t)w * (size_t)N * EMB;
        int qrow = lane >> 2;
        int qcol = (lane & 3) * 2;
#pragma unroll
        for (int t = 0; t < 16; t++) {
            int i = t >> 3, j = t & 7;
            int gr = m0 + wm + i*16 + qrow;
            int gc = wn + j*8 + qcol;
            if (gr < N)
                *reinterpret_cast<float2*>(C + (size_t)gr * EMB + gc) =
                    make_float2(acc[t][0], acc[t][1]);
            int gr2 = gr + 8;
            if (gr2 < N)
                *reinterpret_cast<float2*>(C + (size_t)gr2 * EMB + gc) =
                    make_float2(acc[t][2], acc[t][3]);
        }
    }
}

// ---------------- kernel 2: fused edge pass, 2 edges per warp ----------------
// Each warp handles edges (2p, 2p+1).  Six independent float4 gathers issue
// before any consumer (MLP=6).  After the xor-reduce all 8 lanes of a head
// group hold the head sum, so lane&7==0 posts edge0's norm atomic and
// lane&7==1 posts edge1's (parallel, no extra serialization).
__global__ __launch_bounds__(256) void edge_fused(
    const int* __restrict__ rows, const int* __restrict__ cols,
    float* __restrict__ out, int E, int N)
{
    int pair = (blockIdx.x * blockDim.x + threadIdx.x) >> 5;
    int lane = threadIdx.x & 31;
    int e0 = pair * 2;
    if (e0 >= E) return;
    bool has1 = (e0 + 1) < E;

    int2 rr = *reinterpret_cast<const int2*>(rows + e0);   // rows are adjacent
    int2 cc = *reinterpret_cast<const int2*>(cols + e0);
    int r0 = rr.x, c0 = cc.x;
    int r1 = has1 ? rr.y : rr.x;
    int c1 = has1 ? cc.y : cc.x;

    const float* Q = g_qkv;
    const float* K = g_qkv + (size_t)N * EMB;
    const float* V = g_qkv + 2 * (size_t)N * EMB;
    int d = lane * 4;

    // issue all six gathers up front
    float4 q0 = *reinterpret_cast<const float4*>(Q + (size_t)r0 * EMB + d);
    float4 k0 = *reinterpret_cast<const float4*>(K + (size_t)c0 * EMB + d);
    float4 v0 = *reinterpret_cast<const float4*>(V + (size_t)c0 * EMB + d);
    float4 q1 = *reinterpret_cast<const float4*>(Q + (size_t)r1 * EMB + d);
    float4 k1 = *reinterpret_cast<const float4*>(K + (size_t)c1 * EMB + d);
    float4 v1 = *reinterpret_cast<const float4*>(V + (size_t)c1 * EMB + d);

    float p0 = q0.x * k0.x;
    p0 = fmaf(q0.y, k0.y, p0);
    p0 = fmaf(q0.z, k0.z, p0);
    p0 = fmaf(q0.w, k0.w, p0);
    float p1 = q1.x * k1.x;
    p1 = fmaf(q1.y, k1.y, p1);
    p1 = fmaf(q1.z, k1.z, p1);
    p1 = fmaf(q1.w, k1.w, p1);

    p0 += __shfl_xor_sync(0xffffffffu, p0, 1);
    p1 += __shfl_xor_sync(0xffffffffu, p1, 1);
    p0 += __shfl_xor_sync(0xffffffffu, p0, 2);
    p1 += __shfl_xor_sync(0xffffffffu, p1, 2);
    p0 += __shfl_xor_sync(0xffffffffu, p0, 4);
    p1 += __shfl_xor_sync(0xffffffffu, p1, 4);

    float a0 = __expf(fminf(fmaxf(p0, -10.0f), 10.0f));
    float a1 = __expf(fminf(fmaxf(p1, -10.0f), 10.0f));

    int sub = lane & 7;
    int h   = lane >> 3;
    if (sub == 0)
        atomicAdd(&g_norm[r0 * HEADS + h], a0);
    else if (sub == 1 && has1)
        atomicAdd(&g_norm[r1 * HEADS + h], a1);

    float* op0 = out + (size_t)r0 * EMB + d;
    asm volatile("red.global.add.v4.f32 [%0], {%1, %2, %3, %4};"
                 :: "l"(op0), "f"(a0 * v0.x), "f"(a0 * v0.y),
                    "f"(a0 * v0.z), "f"(a0 * v0.w)
                 : "memory");
    if (has1) {
        float* op1 = out + (size_t)r1 * EMB + d;
        asm volatile("red.global.add.v4.f32 [%0], {%1, %2, %3, %4};"
                     :: "l"(op1), "f"(a1 * v1.x), "f"(a1 * v1.y),
                        "f"(a1 * v1.z), "f"(a1 * v1.w)
                     : "memory");
    }
}

// ---------------- kernel 3: deferred normalization ---------------------------
__global__ __launch_bounds__(256) void scale_kernel(float* __restrict__ out, int N)
{
    int idx = blockIdx.x * blockDim.x + threadIdx.x;
    int total = N * (EMB / 4);
    if (idx >= total) return;
    int n  = idx >> 5;
    int d4 = idx & 31;
    int h  = d4 >> 3;
    float inv = 1.0f / (g_norm[n * HEADS + h] + 1e-8f);
    float4* p = reinterpret_cast<float4*>(out) + idx;
    float4 vv = *p;
    vv.x *= inv; vv.y *= inv; vv.z *= inv; vv.w *= inv;
    *p = vv;
}

// ---------------- launch -----------------------------------------------------
extern "C" void kernel_launch(void* const* d_in, const int* in_sizes, int n_in,
                              void* d_out, int out_size)
{
    const float* embeds = (const float*)d_in[0];
    const float* qW     = (const float*)d_in[1];
    const float* kW     = (const float*)d_in[2];
    const float* vW     = (const float*)d_in[3];
    const int*   rows   = (const int*)d_in[4];
    const int*   cols   = (const int*)d_in[5];

    int N = in_sizes[0] / EMB;
    int E = in_sizes[4];
    float* out = (float*)d_out;

    static bool attr_set = false;
    if (!attr_set) {
        cudaFuncSetAttribute(qkv_gemm_mma,
                             cudaFuncAttributeMaxDynamicSharedMemorySize, SM_TOTAL);
        attr_set = true;
    }

    zero_kernel<<<2048, 256>>>(out, N * EMB, N * HEADS);
    prep_weights<<<(3 * EMB * EMB + 255) / 256, 256>>>(qW, kW, vW);

    int mtiles = (N + 127) / 128;
    qkv_gemm_mma<<<dim3(3, mtiles), 256, SM_TOTAL>>>(embeds, N);

    int pairs   = (E + 1) / 2;
    int eblocks = (pairs + 7) / 8;      // 8 warps (pairs) per 256-thread block
    edge_fused<<<eblocks, 256>>>(rows, cols, out, E, N);

    scale_kernel<<<(N * (EMB / 4) + 255) / 256, 256>>>(out, N);
}